// round 12
// baseline (speedup 1.0000x reference)
#include <cuda_runtime.h>
#include <cuda/atomic>
#include <cstdint>

#define TSTEPS 300
#define HIDN   512
#define EMBD   300
#define G4     2048      // 4*HIDN
#define NCTA   32
#define TPB    512
#define SPIN_GUARD (1 << 16)

typedef unsigned long long u64;

// ---------------- scratch (static __device__, no allocs) ----------------
__device__ __align__(16) float g_pre[TSTEPS * G4]; // input-side gates (+biases)
__device__ __align__(16) u64   g_hw[2][HIDN];      // tagged hidden words: (tag<<32)|bits
                                                   // tag s = "h after s steps"

using dev_atomic_u64 = cuda::atomic_ref<u64, cuda::thread_scope_device>;

__device__ __forceinline__ u64 pack_h(float v, unsigned tag) {
    return ((u64)tag << 32) | (u64)__float_as_uint(v);
}

__device__ __forceinline__ float sigm(float x) { return 1.f / (1.f + __expf(-x)); }
__device__ __forceinline__ float tanh_f(float x) {
    // overflow-safe: tanh(x) = sign(x) * (1 - 2/(exp(2|x|)+1))
    float e = __expf(2.f * fabsf(x));
    float r = 1.f - 2.f / (e + 1.f);
    return copysignf(r, x);
}

// ================= Phase 1: pre[t][row] = W_ih @ emb[x[t]] + b_ih + b_hh ==========
// grid (128, 19), block 256.  Block covers 16 rows x 16 timesteps; K=300 loop.
__global__ void pre_kernel(const int* __restrict__ x,
                           const float* __restrict__ emb,
                           const float* __restrict__ W_ih,
                           const float* __restrict__ b_ih,
                           const float* __restrict__ b_hh,
                           const float* __restrict__ h0)
{
    __shared__ float E[16][301];   // stride 301 -> conflict-free column reads
    const int tB = blockIdx.y * 16;
    const int rB = blockIdx.x * 16;

    for (int idx = threadIdx.x; idx < 16 * EMBD; idx += 256) {
        int tt = idx / EMBD, k = idx % EMBD;
        int t = tB + tt;
        E[tt][k] = (t < TSTEPS) ? emb[(size_t)x[t] * EMBD + k] : 0.f;
    }
    __syncthreads();

    const int t_local = threadIdx.x & 15;
    const int r_local = threadIdx.x >> 4;
    const int r = rB + r_local;
    const int t = tB + t_local;

    const float* wr = W_ih + (size_t)r * EMBD;
    float a0 = 0.f, a1 = 0.f, a2 = 0.f, a3 = 0.f;
    #pragma unroll 4
    for (int k = 0; k < EMBD; k += 4) {
        a0 = fmaf(wr[k + 0], E[t_local][k + 0], a0);
        a1 = fmaf(wr[k + 1], E[t_local][k + 1], a1);
        a2 = fmaf(wr[k + 2], E[t_local][k + 2], a2);
        a3 = fmaf(wr[k + 3], E[t_local][k + 3], a3);
    }
    if (t < TSTEPS)
        g_pre[(size_t)t * G4 + r] = (a0 + a1) + (a2 + a3) + b_ih[r] + b_hh[r];

    // block (0,0): seed h words with tag 0 and poison the other buffer's tags
    // (kills any cross-replay tag collision)
    if (blockIdx.x == 0 && blockIdx.y == 0) {
        for (int i = threadIdx.x; i < HIDN; i += 256) {
            dev_atomic_u64 a0ref(g_hw[0][i]);
            dev_atomic_u64 a1ref(g_hw[1][i]);
            a0ref.store(pack_h(h0[i], 0u), cuda::memory_order_relaxed);
            a1ref.store(((u64)0xFFFFFFFFu << 32), cuda::memory_order_relaxed);
        }
    }
}

// ================= Phase 2: persistent recurrence, warp-per-unit ==================
// 32 CTAs x 512 threads = 512 warps <-> 512 hidden units.  Warp w of CTA c owns
// unit u = 16c + w END-TO-END: all 4 gate rows of u (rows g*512+u), lane l holds
// columns [16l, 16l+16) of each row -> 64 W regs/thread.
// Step: each lane polls its own 16 tagged h-words (batched loads, done-mask);
// 64 FMAs from PRIVATE registers (no shfl in the dot); one 4-value butterfly;
// lanes 0..3 activate the 4 gates in parallel; lane 0 updates c and publishes
// the tagged h word.  NO __syncthreads, NO smem, NO cross-warp coupling in the
// step loop -- 512 independent warp pipelines.
// g_hw overwrite safety (parity): publishing tag s+1 requires having consumed
// every tag-s word, so the tag-s word at g_hw[s&1][*] cannot be overwritten
// (tag s+2, end of the writer's step s+1) before all step-s readers are done.
__global__ void __launch_bounds__(TPB, 1)
lstm_persist(const float* __restrict__ W_hh,
             const float* __restrict__ c0,
             const float* __restrict__ fc_w,
             const float* __restrict__ fc_b,
             float* __restrict__ out)
{
    const int c    = blockIdx.x;
    const int t    = threadIdx.x;
    const int warp = t >> 5;
    const int lane = t & 31;
    const int u    = (c << 4) | warp;      // hidden unit owned by this warp
    const int colb = lane << 4;            // column base: 16*lane

    __shared__ float red[16];              // fc epilogue only

    // ---- load the 4 gate-row slices of unit u into registers (64 floats) ----
    float w[64];                           // w[g*16 + j] = W_hh[g*512+u][colb+j]
    #pragma unroll
    for (int g = 0; g < 4; ++g) {
        const float4* p =
            reinterpret_cast<const float4*>(W_hh + (size_t)(g * HIDN + u) * HIDN + colb);
        #pragma unroll
        for (int i = 0; i < 4; ++i) {
            float4 v = p[i];
            w[g * 16 + 4 * i + 0] = v.x; w[g * 16 + 4 * i + 1] = v.y;
            w[g * 16 + 4 * i + 2] = v.z; w[g * 16 + 4 * i + 3] = v.w;
        }
    }

    float cv = 0.f, hv = 0.f;              // lane-0 state
    if (lane == 0) cv = c0[u];

    for (int step = 0; step < TSTEPS; ++step) {
        const int buf = step & 1;
        const unsigned utag = (unsigned)step;

        // lanes 0..3 prefetch this unit's 4 input-side gate values (in flight
        // during the poll)
        float pre_g = 0.f;
        if (lane < 4) pre_g = __ldg(&g_pre[(size_t)step * G4 + lane * HIDN + u]);

        // ---- poll own 16 tagged words (cols colb..colb+15); batched loads ----
        u64 tmp[16];
        unsigned done = 0;
        {
            int guard = 0;
            do {
                #pragma unroll
                for (int j = 0; j < 16; ++j)
                    if (!(done & (1u << j))) {
                        dev_atomic_u64 r(g_hw[buf][colb + j]);
                        tmp[j] = r.load(cuda::memory_order_relaxed);
                    }
                #pragma unroll
                for (int j = 0; j < 16; ++j)
                    if (!(done & (1u << j)) && (unsigned)(tmp[j] >> 32) == utag)
                        done |= (1u << j);
            } while (done != 0xFFFFu && ++guard < SPIN_GUARD);
        }

        // ---- 64 FMAs from private registers (4 gate accumulators) ----
        float a0 = 0.f, a1 = 0.f, a2 = 0.f, a3 = 0.f;
        #pragma unroll
        for (int j = 0; j < 16; ++j) {
            const float hj = __uint_as_float((unsigned)tmp[j]);
            a0 = fmaf(w[j],      hj, a0);
            a1 = fmaf(w[16 + j], hj, a1);
            a2 = fmaf(w[32 + j], hj, a2);
            a3 = fmaf(w[48 + j], hj, a3);
        }

        // ---- butterfly-reduce the 4 sums across the warp (fixed tree) ----
        #pragma unroll
        for (int o = 16; o > 0; o >>= 1) {
            a0 += __shfl_xor_sync(0xffffffffu, a0, o);
            a1 += __shfl_xor_sync(0xffffffffu, a1, o);
            a2 += __shfl_xor_sync(0xffffffffu, a2, o);
            a3 += __shfl_xor_sync(0xffffffffu, a3, o);
        }

        // ---- lanes 0..3 activate their gate in parallel ----
        float act = 0.f;
        if (lane < 4) {
            float gs = (lane == 0 ? a0 : lane == 1 ? a1 : lane == 2 ? a2 : a3) + pre_g;
            act = (lane == 2) ? tanh_f(gs) : sigm(gs);
        }
        const float i_ = __shfl_sync(0xffffffffu, act, 0);
        const float f_ = __shfl_sync(0xffffffffu, act, 1);
        const float g_ = __shfl_sync(0xffffffffu, act, 2);
        const float o_ = __shfl_sync(0xffffffffu, act, 3);

        // ---- lane 0: cell update + tagged publish ----
        if (lane == 0) {
            float cn = fmaf(f_, cv, i_ * g_);
            cv = cn;
            hv = o_ * tanh_f(cn);
            dev_atomic_u64 hdst(g_hw[buf ^ 1][u]);
            hdst.store(pack_h(hv, (unsigned)(step + 1)), cuda::memory_order_relaxed);
        }
    }

    // ---- outputs: h and c straight from lane-0 registers ----
    if (lane == 0) {
        out[1 + u]   = hv;
        out[513 + u] = cv;
    }

    // ---- CTA 0: final fc once every word carries tag TSTEPS ----
    if (c == 0) {
        float hfin;
        {
            dev_atomic_u64 href(g_hw[TSTEPS & 1][t]);   // TSTEPS even -> buf 0
            u64 word;
            int guard = 0;
            do {
                word = href.load(cuda::memory_order_relaxed);
            } while ((unsigned)(word >> 32) != (unsigned)TSTEPS &&
                     ++guard < SPIN_GUARD);
            hfin = __uint_as_float((unsigned)word);
        }
        float p = hfin * fc_w[t];
        #pragma unroll
        for (int o = 16; o > 0; o >>= 1) p += __shfl_down_sync(0xffffffffu, p, o);
        if ((t & 31) == 0) red[t >> 5] = p;
        __syncthreads();
        if (t == 0) {
            float acc = fc_b[0];
            #pragma unroll
            for (int i = 0; i < 16; ++i) acc += red[i];
            out[0] = sigm(acc);
        }
    }
}

// ================= launch =================
extern "C" void kernel_launch(void* const* d_in, const int* in_sizes, int n_in,
                              void* d_out, int out_size)
{
    const int*   x     = (const int*)  d_in[0];
    const float* h0    = (const float*)d_in[1];
    const float* c0    = (const float*)d_in[2];
    const float* emb   = (const float*)d_in[3];
    const float* W_ih  = (const float*)d_in[4];
    const float* W_hh  = (const float*)d_in[5];
    const float* b_ih  = (const float*)d_in[6];
    const float* b_hh  = (const float*)d_in[7];
    const float* fc_w  = (const float*)d_in[8];
    const float* fc_b  = (const float*)d_in[9];
    float* out = (float*)d_out;

    dim3 pgrid(G4 / 16, (TSTEPS + 15) / 16);   // 128 x 19
    pre_kernel<<<pgrid, 256>>>(x, emb, W_ih, b_ih, b_hh, h0);
    lstm_persist<<<NCTA, TPB>>>(W_hh, c0, fc_w, fc_b, out);
}

// round 13
// speedup vs baseline: 13.0730x; 13.0730x over previous
#include <cuda_runtime.h>
#include <cuda/atomic>
#include <cstdint>

#define TSTEPS 300
#define HIDN   512
#define EMBD   300
#define G4     2048      // 4*HIDN
#define NCTA   32
#define TPB    512
#define SPIN_GUARD (1 << 16)

typedef unsigned long long u64;

// ---------------- scratch (static __device__, no allocs) ----------------
__device__ __align__(16) float g_pre[TSTEPS * G4]; // input-side gates (+biases)
__device__ __align__(16) u64   g_hw[2][HIDN];      // tagged hidden words: (tag<<32)|bits
                                                   // tag s = "h after s steps"

using dev_atomic_u64 = cuda::atomic_ref<u64, cuda::thread_scope_device>;

__device__ __forceinline__ u64 pack_h(float v, unsigned tag) {
    return ((u64)tag << 32) | (u64)__float_as_uint(v);
}

__device__ __forceinline__ float sigm(float x) { return 1.f / (1.f + __expf(-x)); }
__device__ __forceinline__ float tanh_f(float x) {
    // overflow-safe: tanh(x) = sign(x) * (1 - 2/(exp(2|x|)+1))
    float e = __expf(2.f * fabsf(x));
    float r = 1.f - 2.f / (e + 1.f);
    return copysignf(r, x);
}

// ================= Phase 1: pre[t][row] = W_ih @ emb[x[t]] + b_ih + b_hh ==========
// grid (128, 19), block 256.  Block covers 16 rows x 16 timesteps; K=300 loop.
__global__ void pre_kernel(const int* __restrict__ x,
                           const float* __restrict__ emb,
                           const float* __restrict__ W_ih,
                           const float* __restrict__ b_ih,
                           const float* __restrict__ b_hh,
                           const float* __restrict__ h0)
{
    __shared__ float E[16][301];   // stride 301 -> conflict-free column reads
    const int tB = blockIdx.y * 16;
    const int rB = blockIdx.x * 16;

    for (int idx = threadIdx.x; idx < 16 * EMBD; idx += 256) {
        int tt = idx / EMBD, k = idx % EMBD;
        int t = tB + tt;
        E[tt][k] = (t < TSTEPS) ? emb[(size_t)x[t] * EMBD + k] : 0.f;
    }
    __syncthreads();

    const int t_local = threadIdx.x & 15;
    const int r_local = threadIdx.x >> 4;
    const int r = rB + r_local;
    const int t = tB + t_local;

    const float* wr = W_ih + (size_t)r * EMBD;
    float a0 = 0.f, a1 = 0.f, a2 = 0.f, a3 = 0.f;
    #pragma unroll 4
    for (int k = 0; k < EMBD; k += 4) {
        a0 = fmaf(wr[k + 0], E[t_local][k + 0], a0);
        a1 = fmaf(wr[k + 1], E[t_local][k + 1], a1);
        a2 = fmaf(wr[k + 2], E[t_local][k + 2], a2);
        a3 = fmaf(wr[k + 3], E[t_local][k + 3], a3);
    }
    if (t < TSTEPS)
        g_pre[(size_t)t * G4 + r] = (a0 + a1) + (a2 + a3) + b_ih[r] + b_hh[r];

    // block (0,0): seed h words with tag 0 and poison the other buffer's tags
    // (kills any cross-replay tag collision)
    if (blockIdx.x == 0 && blockIdx.y == 0) {
        for (int i = threadIdx.x; i < HIDN; i += 256) {
            dev_atomic_u64 a0ref(g_hw[0][i]);
            dev_atomic_u64 a1ref(g_hw[1][i]);
            a0ref.store(pack_h(h0[i], 0u), cuda::memory_order_relaxed);
            a1ref.store(((u64)0xFFFFFFFFu << 32), cuda::memory_order_relaxed);
        }
    }
}

// ================= Phase 2: persistent recurrence, single-bar hybrid v2 ===========
// 32 CTAs x 512 threads.  CTA c owns hidden units [16c,16c+16) -> 64 gate rows
// (row q: gate = q>>4, unit = q&15).
// Warp-pair p (warps 2p,2p+1) handles all 64 rows x cols [64p, 64p+64); thread
// (pair p, half, lane): row q = half*32+lane; W slice in 64 registers; each lane
// polls TWO tagged L2 h-words with a DEPTH-2 pipelined poll (halves sampling
// staleness at 2x poll traffic -- R12 showed 8x unthrottled saturates, 2x is safe).
// Partials -> s_part[parity][row][chunk] (transposed, stride 9: conflict-free
// writes by chunk and conflict-free 8-chunk gathers by row).
// ONE __syncthreads per step.  Tail after the bar is 64-wide: thread (W in {0,1},
// lane l) handles gate l>>3 of unit W*8+(l&7): 8 LDS + fixed-tree sum + its ONE
// activation (parallel MUFU), in-warp shfl gathers the 4 gates, lanes 0..7 do
// the cell update and publish the tagged h word.
// Safety: s_part parity + bar-gated publishes (tail(s+1) done => tail(s) reads
// done, and overwrite of a parity slot is gated behind tail(s+1) through the
// h-tag chain); g_hw parity via the R7 cross-CTA consume-before-overwrite chain.
__global__ void __launch_bounds__(TPB, 1)
lstm_persist(const float* __restrict__ W_hh,
             const float* __restrict__ c0,
             const float* __restrict__ fc_w,
             const float* __restrict__ fc_b,
             float* __restrict__ out)
{
    const int c    = blockIdx.x;
    const int t    = threadIdx.x;
    const int warp = t >> 5;
    const int lane = t & 31;
    const int pair = warp >> 1;            // 0..7  (column chunk)
    const int half = warp & 1;             // 0/1
    const int q    = (half << 5) | lane;   // row in CTA, 0..63
    const int grow = (q >> 4) * HIDN + (c << 4) + (q & 15);  // global gate row

    const int unitA = (pair << 6) + lane;        // first polled unit
    const int unitB = (pair << 6) + 32 + lane;   // second polled unit

    // tail mapping (threads 0..63): gate tg, local unit tu, row tq
    const int tg = lane >> 3;              // 0..3
    const int tu = ((warp & 1) << 3) | (lane & 7);   // 0..15 (warps 0,1 only)
    const int tq = (tg << 4) | tu;         // row handled by this tail thread

    __shared__ float s_part[2][64][9];     // [parity][row][chunk], stride 9
    __shared__ float red[16];

    // ---- load W_hh slice into registers (kept for all 300 steps) ----
    float w[64];
    {
        const float4* wrow =
            reinterpret_cast<const float4*>(W_hh + (size_t)grow * HIDN + (pair << 6));
        #pragma unroll
        for (int i = 0; i < 16; ++i) {
            float4 v = wrow[i];
            w[4 * i + 0] = v.x; w[4 * i + 1] = v.y;
            w[4 * i + 2] = v.z; w[4 * i + 3] = v.w;
        }
    }

    float cv = 0.f, hv = 0.f;              // state: lanes 0..7 of warps 0,1
    if (t < 64 && (lane >> 3) == 0) cv = c0[(c << 4) + tu];

    for (int step = 0; step < TSTEPS; ++step) {
        const int buf = step & 1;          // h-buffer parity AND s_part parity
        const unsigned utag = (unsigned)step;

        // tail threads prefetch their input-side gate value (in flight during poll)
        float pre_g = 0.f;
        if (t < 64) pre_g = __ldg(&g_pre[(size_t)step * G4 + tg * HIDN + (c << 4) + tu]);

        // ---- depth-2 pipelined poll of the two tagged words ----
        float vA = 0.f, vB = 0.f;
        {
            dev_atomic_u64 ra(g_hw[buf][unitA]);
            dev_atomic_u64 rb(g_hw[buf][unitB]);
            u64 A0 = ra.load(cuda::memory_order_relaxed);
            u64 B0 = rb.load(cuda::memory_order_relaxed);
            u64 A1 = ra.load(cuda::memory_order_relaxed);
            u64 B1 = rb.load(cuda::memory_order_relaxed);
            bool dA = false, dB = false;
            int guard = 0;
            do {
                if (!dA && (unsigned)(A0 >> 32) == utag) { vA = __uint_as_float((unsigned)A0); dA = true; }
                if (!dB && (unsigned)(B0 >> 32) == utag) { vB = __uint_as_float((unsigned)B0); dB = true; }
                if (dA && dB) break;
                if (!dA) { A0 = A1; A1 = ra.load(cuda::memory_order_relaxed); }
                if (!dB) { B0 = B1; B1 = rb.load(cuda::memory_order_relaxed); }
            } while (++guard < SPIN_GUARD);
            if (!dA) vA = __uint_as_float((unsigned)A0);   // guard-expiry fallback
            if (!dB) vB = __uint_as_float((unsigned)B0);
        }

        // ---- 64-MAC dot via shfl broadcast (no smem staging) ----
        float a0 = 0.f, a1 = 0.f, a2 = 0.f, a3 = 0.f;
        #pragma unroll
        for (int k = 0; k < 32; k += 4) {
            a0 = fmaf(w[k + 0], __shfl_sync(0xffffffffu, vA, k + 0), a0);
            a1 = fmaf(w[k + 1], __shfl_sync(0xffffffffu, vA, k + 1), a1);
            a2 = fmaf(w[k + 2], __shfl_sync(0xffffffffu, vA, k + 2), a2);
            a3 = fmaf(w[k + 3], __shfl_sync(0xffffffffu, vA, k + 3), a3);
        }
        #pragma unroll
        for (int k = 0; k < 32; k += 4) {
            a0 = fmaf(w[32 + k + 0], __shfl_sync(0xffffffffu, vB, k + 0), a0);
            a1 = fmaf(w[32 + k + 1], __shfl_sync(0xffffffffu, vB, k + 1), a1);
            a2 = fmaf(w[32 + k + 2], __shfl_sync(0xffffffffu, vB, k + 2), a2);
            a3 = fmaf(w[32 + k + 3], __shfl_sync(0xffffffffu, vB, k + 3), a3);
        }
        s_part[buf][q][pair] = (a0 + a1) + (a2 + a3);

        __syncthreads();                   // the ONLY barrier in the step

        // ---- tail (t<64): reduce own row, activate, gather gates, publish ----
        if (t < 64) {
            const float* pr = s_part[buf][tq];
            float s01 = (pr[0] + pr[1]) + (pr[2] + pr[3]);
            float s23 = (pr[4] + pr[5]) + (pr[6] + pr[7]);
            float gsum = (s01 + s23) + pre_g;
            float act = (tg == 2) ? tanh_f(gsum) : sigm(gsum);

            // gather the 4 gates of unit tu into lanes 0..7 (within this warp)
            const float i_ = __shfl_sync(0xffffffffu, act, (lane & 7) + 0);
            const float f_ = __shfl_sync(0xffffffffu, act, (lane & 7) + 8);
            const float g_ = __shfl_sync(0xffffffffu, act, (lane & 7) + 16);
            const float o_ = __shfl_sync(0xffffffffu, act, (lane & 7) + 24);

            if (tg == 0) {                 // lanes 0..7: cell update + publish
                float cn = fmaf(f_, cv, i_ * g_);
                cv = cn;
                hv = o_ * tanh_f(cn);
                dev_atomic_u64 hdst(g_hw[buf ^ 1][(c << 4) + tu]);
                hdst.store(pack_h(hv, (unsigned)(step + 1)), cuda::memory_order_relaxed);
            }
        }
        // no trailing sync: parity slot reuse (s+2) is bar-gated behind the tail's
        // reads through the h-tag chain (see header comment)
    }

    // ---- outputs: h and c straight from the publishing threads ----
    if (t < 64 && tg == 0) {
        out[1 + ((c << 4) + tu)]   = hv;
        out[513 + ((c << 4) + tu)] = cv;
    }

    // ---- CTA 0: final fc once every word carries tag TSTEPS ----
    if (c == 0) {
        float hfin;
        {
            dev_atomic_u64 href(g_hw[TSTEPS & 1][t]);   // TSTEPS even -> buf 0
            u64 word;
            int guard = 0;
            do {
                word = href.load(cuda::memory_order_relaxed);
            } while ((unsigned)(word >> 32) != (unsigned)TSTEPS &&
                     ++guard < SPIN_GUARD);
            hfin = __uint_as_float((unsigned)word);
        }
        float p = hfin * fc_w[t];
        #pragma unroll
        for (int o = 16; o > 0; o >>= 1) p += __shfl_down_sync(0xffffffffu, p, o);
        if ((t & 31) == 0) red[t >> 5] = p;
        __syncthreads();
        if (t == 0) {
            float acc = fc_b[0];
            #pragma unroll
            for (int i = 0; i < 16; ++i) acc += red[i];
            out[0] = sigm(acc);
        }
    }
}

// ================= launch =================
extern "C" void kernel_launch(void* const* d_in, const int* in_sizes, int n_in,
                              void* d_out, int out_size)
{
    const int*   x     = (const int*)  d_in[0];
    const float* h0    = (const float*)d_in[1];
    const float* c0    = (const float*)d_in[2];
    const float* emb   = (const float*)d_in[3];
    const float* W_ih  = (const float*)d_in[4];
    const float* W_hh  = (const float*)d_in[5];
    const float* b_ih  = (const float*)d_in[6];
    const float* b_hh  = (const float*)d_in[7];
    const float* fc_w  = (const float*)d_in[8];
    const float* fc_b  = (const float*)d_in[9];
    float* out = (float*)d_out;

    dim3 pgrid(G4 / 16, (TSTEPS + 15) / 16);   // 128 x 19
    pre_kernel<<<pgrid, 256>>>(x, emb, W_ih, b_ih, b_hh, h0);
    lstm_persist<<<NCTA, TPB>>>(W_hh, c0, fc_w, fc_b, out);
}